// round 15
// baseline (speedup 1.0000x reference)
#include <cuda_runtime.h>
#include <cuda_fp16.h>
#include <math.h>
#include <stdint.h>

// Problem constants
#define B_ 2
#define T_ 2048
#define C_ 768
#define H_ 12
#define HD_ 64
#define BT_ (B_ * T_)   // 4096

// ---------------------------------------------------------------------------
// Scratch (device globals; no allocation allowed)
// ---------------------------------------------------------------------------
__device__ __half g_ln[BT_ * C_];            // LN output (fp16)
__device__ __half g_qkv[BT_ * 3 * C_];       // QKV (fp16)
__device__ __half g_y[BT_ * C_];             // attention output (fp16)
__device__ float  g_x1[BT_ * C_];            // x + attn (fp32)
__device__ __half g_h[BT_ * 4 * C_];         // gelu(fc) (fp16)
// fp16 transposed weights [N,K]
__device__ __half g_wq[3 * C_ * C_];
__device__ __half g_wa[C_ * C_];
__device__ __half g_wf[4 * C_ * C_];
__device__ __half g_wm[C_ * 4 * C_];

// ---------------------------------------------------------------------------
// Helpers
// ---------------------------------------------------------------------------
__device__ __forceinline__ uint32_t smem_u32(const void* p) {
    uint32_t a;
    asm("{ .reg .u64 t; cvta.to.shared.u64 t, %1; cvt.u32.u64 %0, t; }"
        : "=r"(a) : "l"(p));
    return a;
}

__device__ __forceinline__ uint32_t h2_as_u32(__half2 h) {
    union { __half2 h2; uint32_t u; } cvt;
    cvt.h2 = h;
    return cvt.u;
}

__device__ __forceinline__ float ex2f(float x) {
    float r;
    asm("ex2.approx.f32 %0, %1;" : "=f"(r) : "f"(x));
    return r;
}

#define CP_ASYNC16(dst, src) \
    asm volatile("cp.async.cg.shared.global [%0], [%1], 16;" :: "r"(dst), "l"(src))
#define CP_COMMIT() asm volatile("cp.async.commit_group;" ::: "memory")
#define CP_WAIT(n)  asm volatile("cp.async.wait_group %0;" :: "n"(n) : "memory")

// m16n8k16 f16 inputs, f32 accumulate
__device__ __forceinline__ void mma_f16(float* d, const uint32_t* a, const uint32_t* b) {
    asm volatile(
        "mma.sync.aligned.m16n8k16.row.col.f32.f16.f16.f32 "
        "{%0,%1,%2,%3}, {%4,%5,%6,%7}, {%8,%9}, {%0,%1,%2,%3};"
        : "+f"(d[0]), "+f"(d[1]), "+f"(d[2]), "+f"(d[3])
        : "r"(a[0]), "r"(a[1]), "r"(a[2]), "r"(a[3]), "r"(b[0]), "r"(b[1]));
}

__device__ __forceinline__ void ldsm_x4(uint32_t* r, uint32_t a) {
    asm volatile("ldmatrix.sync.aligned.m8n8.x4.shared.b16 {%0,%1,%2,%3}, [%4];"
        : "=r"(r[0]), "=r"(r[1]), "=r"(r[2]), "=r"(r[3]) : "r"(a));
}
__device__ __forceinline__ void ldsm_x4_t(uint32_t* r, uint32_t a) {
    asm volatile("ldmatrix.sync.aligned.m8n8.x4.trans.shared.b16 {%0,%1,%2,%3}, [%4];"
        : "=r"(r[0]), "=r"(r[1]), "=r"(r[2]), "=r"(r[3]) : "r"(a));
}

// ---------------------------------------------------------------------------
// Fused weight transpose+convert (all four weights, one launch).
// ---------------------------------------------------------------------------
#define WT_QKV 1728
#define WT_A   576
#define WT_FC  2304
#define WT_MLP 2304
#define WT_TOT (WT_QKV + WT_A + WT_FC + WT_MLP)

__global__ void wconv_all(const float* __restrict__ iq, const float* __restrict__ ia,
                          const float* __restrict__ ifc, const float* __restrict__ im,
                          __half* __restrict__ oq, __half* __restrict__ oa,
                          __half* __restrict__ ofc, __half* __restrict__ om) {
    __shared__ float tile[32][33];
    int t = blockIdx.x;
    const float* in;
    __half* out;
    int K, N;
    if (t < WT_QKV) { in = iq; out = oq; K = C_; N = 3 * C_; }
    else if (t < WT_QKV + WT_A) { t -= WT_QKV; in = ia; out = oa; K = C_; N = C_; }
    else if (t < WT_QKV + WT_A + WT_FC) { t -= WT_QKV + WT_A; in = ifc; out = ofc; K = C_; N = 4 * C_; }
    else { t -= WT_QKV + WT_A + WT_FC; in = im; out = om; K = 4 * C_; N = C_; }
    int tiles_n = N >> 5;
    int n0 = (t % tiles_n) << 5, k0 = (t / tiles_n) << 5;
#pragma unroll
    for (int i = threadIdx.y; i < 32; i += 8)
        tile[i][threadIdx.x] = in[(size_t)(k0 + i) * N + n0 + threadIdx.x];
    __syncthreads();
#pragma unroll
    for (int i = threadIdx.y; i < 32; i += 8)
        out[(size_t)(n0 + i) * K + k0 + threadIdx.x] = __float2half_rn(tile[threadIdx.x][i]);
}

// ---------------------------------------------------------------------------
// LayerNorm: warp per row, float4, warp-only reduction. Output fp16.
// ---------------------------------------------------------------------------
__global__ void ln_kernel(const float* __restrict__ x, const float* __restrict__ g,
                          const float* __restrict__ b, __half* __restrict__ out) {
    int row = blockIdx.x * 8 + (threadIdx.x >> 5);
    int lane = threadIdx.x & 31;
    const float4* xr = (const float4*)(x + (size_t)row * C_);
    float4 v[6];
    float s = 0.f, sq = 0.f;
#pragma unroll
    for (int i = 0; i < 6; i++) {
        v[i] = xr[lane + i * 32];
        s  += v[i].x + v[i].y + v[i].z + v[i].w;
        sq += v[i].x * v[i].x + v[i].y * v[i].y + v[i].z * v[i].z + v[i].w * v[i].w;
    }
#pragma unroll
    for (int off = 16; off; off >>= 1) {
        s  += __shfl_xor_sync(0xffffffffu, s, off);
        sq += __shfl_xor_sync(0xffffffffu, sq, off);
    }
    float mean = s * (1.0f / C_);
    float var  = sq * (1.0f / C_) - mean * mean;
    float rstd = rsqrtf(var + 1e-5f);
    const float4* g4 = (const float4*)g;
    const float4* b4 = (const float4*)b;
    uint2* o8 = (uint2*)(out + (size_t)row * C_);
#pragma unroll
    for (int i = 0; i < 6; i++) {
        int idx = lane + i * 32;
        float4 gv = g4[idx], bv = b4[idx];
        float r0 = (v[i].x - mean) * rstd * gv.x + bv.x;
        float r1 = (v[i].y - mean) * rstd * gv.y + bv.y;
        float r2 = (v[i].z - mean) * rstd * gv.z + bv.z;
        float r3 = (v[i].w - mean) * rstd * gv.w + bv.w;
        uint2 u;
        u.x = h2_as_u32(__floats2half2_rn(r0, r1));
        u.y = h2_as_u32(__floats2half2_rn(r2, r3));
        o8[idx] = u;
    }
}

// ---------------------------------------------------------------------------
// f16 GEMM: C[M,N] = A[M,K] @ Wt[N,K]^T, fp16 in, fp32 accumulate.
// BM=128, BN template (128/64), BK=64, 3-stage cp.async, 256 threads.
// KB (= K/64) template param; unroll-by-3 const-folds stage addressing.
// EPI: 0 = half out, 1 = float out += res, 2 = GELU -> half out
// ---------------------------------------------------------------------------
#define A_STAGE_BYTES 16384
template <int BN> struct GemmCfg {
    static const int B_STAGE_BYTES = BN * 128;
    static const int STAGE_BYTES = A_STAGE_BYTES + B_STAGE_BYTES;
    static const int SMEM = 3 * STAGE_BYTES;
    static const int MT = (BN == 128) ? 4 : 2;
};

template <int BN, int KB>
__device__ __forceinline__ void load_stage(uint32_t sa, uint32_t sb,
                                           const __half* __restrict__ Ab,
                                           const __half* __restrict__ Wb,
                                           int kb, int tid) {
    const int K = KB * 64;
    int k0 = kb * 64;
#pragma unroll
    for (int t = 0; t < 4; t++) {
        int linear = tid + t * 256;
        int m = linear >> 3, c = linear & 7;
        uint32_t sw = (uint32_t)((m * 32 + ((c * 4) ^ ((m & 7) << 2))) * 4);
        CP_ASYNC16(sa + sw, Ab + (size_t)m * K + k0 + c * 8);
    }
#pragma unroll
    for (int t = 0; t < BN / 32; t++) {
        int linear = tid + t * 256;
        int m = linear >> 3, c = linear & 7;
        uint32_t sw = (uint32_t)((m * 32 + ((c * 4) ^ ((m & 7) << 2))) * 4);
        CP_ASYNC16(sb + sw, Wb + (size_t)m * K + k0 + c * 8);
    }
}

template <int EPI, int BN, int KB>
__global__ __launch_bounds__(256, 2)
void tc_gemm(const __half* __restrict__ A, const __half* __restrict__ Wt,
             const float* __restrict__ res, void* __restrict__ Cm,
             int M, int N) {
    typedef GemmCfg<BN> CFG;
    const int MT = CFG::MT;
    const int K = KB * 64;
    extern __shared__ __align__(16) char dsm[];
    uint32_t sbase = smem_u32(dsm);

    int tid = threadIdx.x;
    int wid = tid >> 5, lane = tid & 31;
    int warp_m, warp_n;
    if (BN == 128) { warp_m = wid >> 2; warp_n = wid & 3; }
    else           { warp_m = wid >> 1; warp_n = wid & 1; }
    int lr = lane >> 2, lc = lane & 3;

    int swl = (lane & 7) << 2;
    int arow = warp_m * (MT * 16) + (lane & 15);
    uint32_t ahi4 = (uint32_t)((lane >> 4) * 4);
    int brow = warp_n * 32 + ((lane >> 4) << 3) + (lane & 7);
    uint32_t bhi4 = (uint32_t)(((lane >> 3) & 1) * 4);

    const __half* Ab = A + (size_t)blockIdx.y * 128 * K;
    const __half* Wb = Wt + (size_t)blockIdx.x * BN * K;

    float acc[CFG::MT][4][4];
#pragma unroll
    for (int i = 0; i < MT; i++)
#pragma unroll
        for (int j = 0; j < 4; j++)
#pragma unroll
            for (int r = 0; r < 4; r++) acc[i][j][r] = 0.f;

    load_stage<BN, KB>(sbase, sbase + A_STAGE_BYTES, Ab, Wb, 0, tid);
    CP_COMMIT();
    load_stage<BN, KB>(sbase + CFG::STAGE_BYTES, sbase + CFG::STAGE_BYTES + A_STAGE_BYTES,
                       Ab, Wb, 1, tid);
    CP_COMMIT();

#pragma unroll 3
    for (int kb = 0; kb < KB; kb++) {
        int s = kb % 3;
        if (kb + 1 < KB) { CP_WAIT(1); } else { CP_WAIT(0); }
        __syncthreads();
        if (kb + 2 < KB) {
            int sn = (kb + 2) % 3;
            load_stage<BN, KB>(sbase + sn * CFG::STAGE_BYTES,
                               sbase + sn * CFG::STAGE_BYTES + A_STAGE_BYTES,
                               Ab, Wb, kb + 2, tid);
            CP_COMMIT();
        }

        uint32_t as_addr = sbase + s * CFG::STAGE_BYTES;
        uint32_t bs_addr = as_addr + A_STAGE_BYTES;
#pragma unroll
        for (int ks = 0; ks < 4; ks++) {
            uint32_t wa = (uint32_t)(((ks * 8 + ahi4) ^ swl) * 4);
            uint32_t wb = (uint32_t)(((ks * 8 + bhi4) ^ swl) * 4);
            uint32_t afr[CFG::MT][4], bfr[2][4];
#pragma unroll
            for (int mt = 0; mt < MT; mt++)
                ldsm_x4(afr[mt], as_addr + (uint32_t)(arow + mt * 16) * 128 + wa);
#pragma unroll
            for (int ntp = 0; ntp < 2; ntp++)
                ldsm_x4(bfr[ntp], bs_addr + (uint32_t)(brow + ntp * 16) * 128 + wb);
#pragma unroll
            for (int mt = 0; mt < MT; mt++)
#pragma unroll
                for (int nt = 0; nt < 4; nt++)
                    mma_f16(acc[mt][nt], afr[mt], bfr[nt >> 1] + 2 * (nt & 1));
        }
    }

    __syncthreads();
    int gm0 = blockIdx.y * 128 + warp_m * (MT * 16);
    int gn0 = blockIdx.x * BN + warp_n * 32;
#pragma unroll
    for (int mt = 0; mt < MT; mt++) {
#pragma unroll
        for (int nt = 0; nt < 4; nt++) {
            int gm = gm0 + mt * 16 + lr;
            int gn = gn0 + nt * 8 + lc * 2;
#pragma unroll
            for (int half_ = 0; half_ < 2; half_++) {
                int row = gm + half_ * 8;
                size_t off = (size_t)row * N + gn;
                float vx = acc[mt][nt][half_ * 2 + 0];
                float vy = acc[mt][nt][half_ * 2 + 1];
                if (EPI == 1) {
                    float2 rs = *(const float2*)(res + off);
                    float2 v = make_float2(vx + rs.x, vy + rs.y);
                    *(float2*)((float*)Cm + off) = v;
                } else if (EPI == 2) {
                    vx = 0.5f * vx * (1.0f + erff(vx * 0.7071067811865475f));
                    vy = 0.5f * vy * (1.0f + erff(vy * 0.7071067811865475f));
                    *(__half2*)((__half*)Cm + off) = __floats2half2_rn(vx, vy);
                } else {
                    *(__half2*)((__half*)Cm + off) = __floats2half2_rn(vx, vy);
                }
            }
        }
    }
}

// ---------------------------------------------------------------------------
// Tensor-core flash attention (fp16 in / fp32 accum, causal).
// Grid: (T/64, B*H), 128 threads, occupancy 4. Softmax in exp2 domain.
// smem halfs: Q [0,4096) | P [4096,8192) | K[2] [8192,16384) | V[2] [16384,24576)
// ---------------------------------------------------------------------------
#define ATTN_SMEM (24576 * 2)   // 48KB

__device__ __forceinline__ void attn_load_kv(uint32_t sb, const __half* __restrict__ kbase,
                                             const __half* __restrict__ vbase,
                                             int j, int s, int tid) {
    uint32_t kdst = sb + (uint32_t)(8192 + s * 4096) * 2;
    uint32_t vdst = sb + (uint32_t)(16384 + s * 4096) * 2;
#pragma unroll
    for (int t = 0; t < 4; t++) {
        int linear = tid + t * 128;
        int r = linear >> 3, c = linear & 7;
        uint32_t sw = (uint32_t)((r * 32 + ((c * 4) ^ ((r & 7) << 2))) * 4);
        size_t go = (size_t)(j * 64 + r) * 3 * C_ + c * 8;
        CP_ASYNC16(kdst + sw, kbase + go);
        CP_ASYNC16(vdst + sw, vbase + go);
    }
}

__global__ __launch_bounds__(128, 4)
void attn_tc(const __half* __restrict__ qkv, __half* __restrict__ y) {
    extern __shared__ __align__(16) char smc[];
    uint32_t sb = smem_u32(smc);

    int qb = gridDim.x - 1 - blockIdx.x;  // longest blocks first
    int bh = blockIdx.y;
    int b = bh / H_, h = bh % H_;
    int tid = threadIdx.x, wid = tid >> 5, lane = tid & 31;
    int lr = lane >> 2, lc = lane & 3;

    const __half* qbase = qkv + (size_t)b * T_ * 3 * C_ + h * HD_;
    const __half* kbase = qbase + C_;
    const __half* vbase = qbase + 2 * C_;

    // load Q tile
#pragma unroll
    for (int t = 0; t < 4; t++) {
        int linear = tid + t * 128;
        int r = linear >> 3, c = linear & 7;
        uint32_t sw = (uint32_t)((r * 32 + ((c * 4) ^ ((r & 7) << 2))) * 4);
        CP_ASYNC16(sb + sw, qbase + (size_t)(qb * 64 + r) * 3 * C_ + c * 8);
    }
    CP_COMMIT();
    attn_load_kv(sb, kbase, vbase, 0, 0, tid);
    CP_COMMIT();

    CP_WAIT(1);
    __syncthreads();

    // ldmatrix constants
    int swl = (lane & 7) << 2;
    int arow = wid * 16 + (lane & 15);
    uint32_t ahi4 = (uint32_t)((lane >> 4) * 4);
    int brow = ((lane >> 4) << 3) + (lane & 7);
    uint32_t bhi4 = (uint32_t)(((lane >> 3) & 1) * 4);
    int vtloc = (((lane >> 3) & 1) << 3) + (lane & 7);
    uint32_t vdc = (uint32_t)(lane >> 4);

    // Q fragments
    uint32_t qfr[4][4];
#pragma unroll
    for (int ks = 0; ks < 4; ks++) {
        uint32_t w = (uint32_t)(((ks * 8 + ahi4) ^ swl) * 4);
        ldsm_x4(qfr[ks], sb + (uint32_t)arow * 128 + w);
    }

    float oacc[8][4];
#pragma unroll
    for (int i = 0; i < 8; i++)
#pragma unroll
        for (int e = 0; e < 4; e++) oacc[i][e] = 0.f;
    float m0 = -1e30f, m1 = -1e30f, l0 = 0.f, l1 = 0.f;

    int r0 = wid * 16 + lr;
    int rg0 = qb * 64 + r0;
    uint32_t psm = sb + 4096 * 2;
    uint32_t* p32 = (uint32_t*)(smc) + 2048;

    // scale folded with log2e: softmax runs in exp2 domain
    const float SC = 0.125f * 1.4426950408889634f;

    for (int j = 0; j <= qb; j++) {
        int s = j & 1;
        if (j < qb) {
            attn_load_kv(sb, kbase, vbase, j + 1, s ^ 1, tid);
            CP_COMMIT();
            CP_WAIT(1);
        } else {
            CP_WAIT(0);
        }
        __syncthreads();

        uint32_t ksm = sb + (uint32_t)(8192 + s * 4096) * 2;
        uint32_t vsm = sb + (uint32_t)(16384 + s * 4096) * 2;

        // S = Q @ K^T
        float sacc[8][4];
#pragma unroll
        for (int nf = 0; nf < 8; nf++)
#pragma unroll
            for (int e = 0; e < 4; e++) sacc[nf][e] = 0.f;
#pragma unroll
        for (int ks = 0; ks < 4; ks++) {
            uint32_t wb = (uint32_t)(((ks * 8 + bhi4) ^ swl) * 4);
#pragma unroll
            for (int ntp = 0; ntp < 4; ntp++) {
                uint32_t kf[4];
                ldsm_x4(kf, ksm + (uint32_t)(brow + ntp * 16) * 128 + wb);
                mma_f16(sacc[2 * ntp],     qfr[ks], kf);
                mma_f16(sacc[2 * ntp + 1], qfr[ks], kf + 2);
            }
        }

        // scale (log2 domain) + causal mask (diagonal tile only)
#pragma unroll
        for (int nf = 0; nf < 8; nf++) {
#pragma unroll
            for (int e = 0; e < 4; e++) {
                float v = sacc[nf][e] * SC;
                if (j == qb) {
                    int col = j * 64 + nf * 8 + 2 * lc + (e & 1);
                    int row = (e < 2) ? rg0 : rg0 + 8;
                    if (col > row) v = -1e30f;
                }
                sacc[nf][e] = v;
            }
        }

        // online softmax (exp2 domain)
        float ml0 = -1e30f, ml1 = -1e30f;
#pragma unroll
        for (int nf = 0; nf < 8; nf++) {
            ml0 = fmaxf(ml0, fmaxf(sacc[nf][0], sacc[nf][1]));
            ml1 = fmaxf(ml1, fmaxf(sacc[nf][2], sacc[nf][3]));
        }
#pragma unroll
        for (int off = 1; off < 4; off <<= 1) {
            ml0 = fmaxf(ml0, __shfl_xor_sync(0xffffffffu, ml0, off));
            ml1 = fmaxf(ml1, __shfl_xor_sync(0xffffffffu, ml1, off));
        }
        float mn0 = fmaxf(m0, ml0), mn1 = fmaxf(m1, ml1);
        float c0 = ex2f(m0 - mn0), c1 = ex2f(m1 - mn1);
        float ls0 = 0.f, ls1 = 0.f;
        int swq = (r0 & 7) << 2;
#pragma unroll
        for (int nf = 0; nf < 8; nf++) {
            float p0 = ex2f(sacc[nf][0] - mn0);
            float p1 = ex2f(sacc[nf][1] - mn0);
            float p2 = ex2f(sacc[nf][2] - mn1);
            float p3 = ex2f(sacc[nf][3] - mn1);
            ls0 += p0 + p1;
            ls1 += p2 + p3;
            int wp = nf * 4 + lc;
            p32[r0 * 32 + (wp ^ swq)]       = h2_as_u32(__floats2half2_rn(p0, p1));
            p32[(r0 + 8) * 32 + (wp ^ swq)] = h2_as_u32(__floats2half2_rn(p2, p3));
        }
#pragma unroll
        for (int off = 1; off < 4; off <<= 1) {
            ls0 += __shfl_xor_sync(0xffffffffu, ls0, off);
            ls1 += __shfl_xor_sync(0xffffffffu, ls1, off);
        }
        l0 = l0 * c0 + ls0;
        l1 = l1 * c1 + ls1;
        m0 = mn0; m1 = mn1;
#pragma unroll
        for (int nf = 0; nf < 8; nf++) {
            oacc[nf][0] *= c0;
            oacc[nf][1] *= c0;
            oacc[nf][2] *= c1;
            oacc[nf][3] *= c1;
        }
        __syncwarp();

        // O += P @ V
#pragma unroll
        for (int ks = 0; ks < 4; ks++) {
            uint32_t pafr[4];
            uint32_t wp = (uint32_t)(((ks * 8 + ahi4) ^ swl) * 4);
            ldsm_x4(pafr, psm + (uint32_t)arow * 128 + wp);
            int trow = ks * 16 + vtloc;
            uint32_t vbaseaddr = vsm + (uint32_t)trow * 128;
            uint32_t vswl = (uint32_t)((trow & 7) << 2);
#pragma unroll
            for (int nfp = 0; nfp < 4; nfp++) {
                uint32_t vf[4];
                uint32_t wv = (uint32_t)((((2 * nfp + vdc) * 4) ^ vswl) * 4);
                ldsm_x4_t(vf, vbaseaddr + wv);
                mma_f16(oacc[2 * nfp],     pafr, vf);
                mma_f16(oacc[2 * nfp + 1], pafr, vf + 2);
            }
        }
        __syncthreads();
    }

    // write y (fp16)
    float inv0 = 1.0f / l0, inv1 = 1.0f / l1;
#pragma unroll
    for (int nf = 0; nf < 8; nf++) {
        int gc = h * HD_ + nf * 8 + 2 * lc;
        size_t o0 = (size_t)(b * T_ + rg0) * C_ + gc;
        size_t o1 = (size_t)(b * T_ + rg0 + 8) * C_ + gc;
        *(__half2*)(y + o0) = __floats2half2_rn(oacc[nf][0] * inv0, oacc[nf][1] * inv0);
        *(__half2*)(y + o1) = __floats2half2_rn(oacc[nf][2] * inv1, oacc[nf][3] * inv1);
    }
}

// ---------------------------------------------------------------------------
// Launch
// ---------------------------------------------------------------------------
extern "C" void kernel_launch(void* const* d_in, const int* in_sizes, int n_in,
                              void* d_out, int out_size) {
    const float* x       = (const float*)d_in[0];
    const float* ln1_g   = (const float*)d_in[1];
    const float* ln1_b   = (const float*)d_in[2];
    const float* W_qkv   = (const float*)d_in[3];
    const float* W_attn  = (const float*)d_in[4];
    const float* ln2_g   = (const float*)d_in[5];
    const float* ln2_b   = (const float*)d_in[6];
    const float* W_fc    = (const float*)d_in[7];
    const float* W_mlp   = (const float*)d_in[8];
    float* out = (float*)d_out;

    __half *ln, *qkv, *yb, *hb, *wq, *wa, *wf, *wm;
    float* x1;
    cudaGetSymbolAddress((void**)&ln, g_ln);
    cudaGetSymbolAddress((void**)&qkv, g_qkv);
    cudaGetSymbolAddress((void**)&yb, g_y);
    cudaGetSymbolAddress((void**)&x1, g_x1);
    cudaGetSymbolAddress((void**)&hb, g_h);
    cudaGetSymbolAddress((void**)&wq, g_wq);
    cudaGetSymbolAddress((void**)&wa, g_wa);
    cudaGetSymbolAddress((void**)&wf, g_wf);
    cudaGetSymbolAddress((void**)&wm, g_wm);

    cudaFuncSetAttribute((tc_gemm<0, 128, 12>), cudaFuncAttributeMaxDynamicSharedMemorySize, GemmCfg<128>::SMEM);
    cudaFuncSetAttribute((tc_gemm<2, 128, 12>), cudaFuncAttributeMaxDynamicSharedMemorySize, GemmCfg<128>::SMEM);
    cudaFuncSetAttribute((tc_gemm<1, 64, 12>),  cudaFuncAttributeMaxDynamicSharedMemorySize, GemmCfg<64>::SMEM);
    cudaFuncSetAttribute((tc_gemm<1, 64, 48>),  cudaFuncAttributeMaxDynamicSharedMemorySize, GemmCfg<64>::SMEM);
    cudaFuncSetAttribute(attn_tc, cudaFuncAttributeMaxDynamicSharedMemorySize, ATTN_SMEM);

    // 0) weights -> fp16 [N,K], single launch
    wconv_all<<<WT_TOT, dim3(32, 8)>>>(W_qkv, W_attn, W_fc, W_mlp, wq, wa, wf, wm);

    // 1) LN1 -> fp16
    ln_kernel<<<BT_ / 8, 256>>>(x, ln1_g, ln1_b, ln);
    // 2) QKV = ln1 @ W_qkv -> fp16
    tc_gemm<0, 128, 12><<<dim3(3 * C_ / 128, BT_ / 128), 256, GemmCfg<128>::SMEM>>>(
        ln, wq, nullptr, qkv, BT_, 3 * C_);
    // 3) causal flash attention (fp16 mma, ldmatrix, exp2 softmax)
    attn_tc<<<dim3(T_ / 64, B_ * H_), 128, ATTN_SMEM>>>(qkv, yb);
    // 4) x1 = x + y @ W_attn_proj (fp32 out), BN=64
    tc_gemm<1, 64, 12><<<dim3(C_ / 64, BT_ / 128), 256, GemmCfg<64>::SMEM>>>(
        yb, wa, x, x1, BT_, C_);
    // 5) LN2 -> fp16
    ln_kernel<<<BT_ / 8, 256>>>(x1, ln2_g, ln2_b, ln);
    // 6) h = gelu(ln2 @ W_fc) -> fp16
    tc_gemm<2, 128, 12><<<dim3(4 * C_ / 128, BT_ / 128), 256, GemmCfg<128>::SMEM>>>(
        ln, wf, nullptr, hb, BT_, 4 * C_);
    // 7) out = x1 + h @ W_mlp_proj (fp32 out), BN=64
    tc_gemm<1, 64, 48><<<dim3(C_ / 64, BT_ / 128), 256, GemmCfg<64>::SMEM>>>(
        hb, wm, x1, out, BT_, C_);
}

// round 16
// speedup vs baseline: 1.0217x; 1.0217x over previous
#include <cuda_runtime.h>
#include <cuda_fp16.h>
#include <math.h>
#include <stdint.h>

// Problem constants
#define B_ 2
#define T_ 2048
#define C_ 768
#define H_ 12
#define HD_ 64
#define BT_ (B_ * T_)   // 4096

// ---------------------------------------------------------------------------
// Scratch (device globals; no allocation allowed)
// ---------------------------------------------------------------------------
__device__ __half g_ln[BT_ * C_];            // LN output (fp16)
__device__ __half g_qkv[BT_ * 3 * C_];       // QKV (fp16)
__device__ __half g_y[BT_ * C_];             // attention output (fp16)
__device__ float  g_x1[BT_ * C_];            // x + attn (fp32)
__device__ __half g_h[BT_ * 4 * C_];         // gelu(fc) (fp16)
// fp16 transposed weights [N,K]
__device__ __half g_wq[3 * C_ * C_];
__device__ __half g_wa[C_ * C_];
__device__ __half g_wf[4 * C_ * C_];
__device__ __half g_wm[C_ * 4 * C_];

// ---------------------------------------------------------------------------
// Helpers
// ---------------------------------------------------------------------------
__device__ __forceinline__ uint32_t smem_u32(const void* p) {
    uint32_t a;
    asm("{ .reg .u64 t; cvta.to.shared.u64 t, %1; cvt.u32.u64 %0, t; }"
        : "=r"(a) : "l"(p));
    return a;
}

__device__ __forceinline__ uint32_t h2_as_u32(__half2 h) {
    union { __half2 h2; uint32_t u; } cvt;
    cvt.h2 = h;
    return cvt.u;
}

__device__ __forceinline__ float ex2f(float x) {
    float r;
    asm("ex2.approx.f32 %0, %1;" : "=f"(r) : "f"(x));
    return r;
}

#define CP_ASYNC16(dst, src) \
    asm volatile("cp.async.cg.shared.global [%0], [%1], 16;" :: "r"(dst), "l"(src))
#define CP_COMMIT() asm volatile("cp.async.commit_group;" ::: "memory")
#define CP_WAIT(n)  asm volatile("cp.async.wait_group %0;" :: "n"(n) : "memory")

// m16n8k16 f16 inputs, f32 accumulate
__device__ __forceinline__ void mma_f16(float* d, const uint32_t* a, const uint32_t* b) {
    asm volatile(
        "mma.sync.aligned.m16n8k16.row.col.f32.f16.f16.f32 "
        "{%0,%1,%2,%3}, {%4,%5,%6,%7}, {%8,%9}, {%0,%1,%2,%3};"
        : "+f"(d[0]), "+f"(d[1]), "+f"(d[2]), "+f"(d[3])
        : "r"(a[0]), "r"(a[1]), "r"(a[2]), "r"(a[3]), "r"(b[0]), "r"(b[1]));
}

__device__ __forceinline__ void ldsm_x4(uint32_t* r, uint32_t a) {
    asm volatile("ldmatrix.sync.aligned.m8n8.x4.shared.b16 {%0,%1,%2,%3}, [%4];"
        : "=r"(r[0]), "=r"(r[1]), "=r"(r[2]), "=r"(r[3]) : "r"(a));
}
__device__ __forceinline__ void ldsm_x4_t(uint32_t* r, uint32_t a) {
    asm volatile("ldmatrix.sync.aligned.m8n8.x4.trans.shared.b16 {%0,%1,%2,%3}, [%4];"
        : "=r"(r[0]), "=r"(r[1]), "=r"(r[2]), "=r"(r[3]) : "r"(a));
}

// ---------------------------------------------------------------------------
// Fused weight transpose+convert (all four weights, one launch).
// ---------------------------------------------------------------------------
#define WT_QKV 1728
#define WT_A   576
#define WT_FC  2304
#define WT_MLP 2304
#define WT_TOT (WT_QKV + WT_A + WT_FC + WT_MLP)

__global__ void wconv_all(const float* __restrict__ iq, const float* __restrict__ ia,
                          const float* __restrict__ ifc, const float* __restrict__ im,
                          __half* __restrict__ oq, __half* __restrict__ oa,
                          __half* __restrict__ ofc, __half* __restrict__ om) {
    __shared__ float tile[32][33];
    int t = blockIdx.x;
    const float* in;
    __half* out;
    int K, N;
    if (t < WT_QKV) { in = iq; out = oq; K = C_; N = 3 * C_; }
    else if (t < WT_QKV + WT_A) { t -= WT_QKV; in = ia; out = oa; K = C_; N = C_; }
    else if (t < WT_QKV + WT_A + WT_FC) { t -= WT_QKV + WT_A; in = ifc; out = ofc; K = C_; N = 4 * C_; }
    else { t -= WT_QKV + WT_A + WT_FC; in = im; out = om; K = 4 * C_; N = C_; }
    int tiles_n = N >> 5;
    int n0 = (t % tiles_n) << 5, k0 = (t / tiles_n) << 5;
#pragma unroll
    for (int i = threadIdx.y; i < 32; i += 8)
        tile[i][threadIdx.x] = in[(size_t)(k0 + i) * N + n0 + threadIdx.x];
    __syncthreads();
#pragma unroll
    for (int i = threadIdx.y; i < 32; i += 8)
        out[(size_t)(n0 + i) * K + k0 + threadIdx.x] = __float2half_rn(tile[threadIdx.x][i]);
}

// ---------------------------------------------------------------------------
// LayerNorm: warp per row, float4, warp-only reduction. Output fp16.
// ---------------------------------------------------------------------------
__global__ void ln_kernel(const float* __restrict__ x, const float* __restrict__ g,
                          const float* __restrict__ b, __half* __restrict__ out) {
    int row = blockIdx.x * 8 + (threadIdx.x >> 5);
    int lane = threadIdx.x & 31;
    const float4* xr = (const float4*)(x + (size_t)row * C_);
    float4 v[6];
    float s = 0.f, sq = 0.f;
#pragma unroll
    for (int i = 0; i < 6; i++) {
        v[i] = xr[lane + i * 32];
        s  += v[i].x + v[i].y + v[i].z + v[i].w;
        sq += v[i].x * v[i].x + v[i].y * v[i].y + v[i].z * v[i].z + v[i].w * v[i].w;
    }
#pragma unroll
    for (int off = 16; off; off >>= 1) {
        s  += __shfl_xor_sync(0xffffffffu, s, off);
        sq += __shfl_xor_sync(0xffffffffu, sq, off);
    }
    float mean = s * (1.0f / C_);
    float var  = sq * (1.0f / C_) - mean * mean;
    float rstd = rsqrtf(var + 1e-5f);
    const float4* g4 = (const float4*)g;
    const float4* b4 = (const float4*)b;
    uint2* o8 = (uint2*)(out + (size_t)row * C_);
#pragma unroll
    for (int i = 0; i < 6; i++) {
        int idx = lane + i * 32;
        float4 gv = g4[idx], bv = b4[idx];
        float r0 = (v[i].x - mean) * rstd * gv.x + bv.x;
        float r1 = (v[i].y - mean) * rstd * gv.y + bv.y;
        float r2 = (v[i].z - mean) * rstd * gv.z + bv.z;
        float r3 = (v[i].w - mean) * rstd * gv.w + bv.w;
        uint2 u;
        u.x = h2_as_u32(__floats2half2_rn(r0, r1));
        u.y = h2_as_u32(__floats2half2_rn(r2, r3));
        o8[idx] = u;
    }
}

// ---------------------------------------------------------------------------
// f16 GEMM: C[M,N] = A[M,K] @ Wt[N,K]^T, fp16 in, fp32 accumulate.
// BM=128, BN template (128/64), BK=64, 3-stage cp.async, 256 threads.
// KB (= K/64) template param; unroll-by-3 const-folds stage addressing.
// EPI: 0 = half out, 1 = float out += res, 2 = GELU -> half out
// ---------------------------------------------------------------------------
#define A_STAGE_BYTES 16384
template <int BN> struct GemmCfg {
    static const int B_STAGE_BYTES = BN * 128;
    static const int STAGE_BYTES = A_STAGE_BYTES + B_STAGE_BYTES;
    static const int SMEM = 3 * STAGE_BYTES;
    static const int MT = (BN == 128) ? 4 : 2;
};

template <int BN, int KB>
__device__ __forceinline__ void load_stage(uint32_t sa, uint32_t sb,
                                           const __half* __restrict__ Ab,
                                           const __half* __restrict__ Wb,
                                           int kb, int tid) {
    const int K = KB * 64;
    int k0 = kb * 64;
#pragma unroll
    for (int t = 0; t < 4; t++) {
        int linear = tid + t * 256;
        int m = linear >> 3, c = linear & 7;
        uint32_t sw = (uint32_t)((m * 32 + ((c * 4) ^ ((m & 7) << 2))) * 4);
        CP_ASYNC16(sa + sw, Ab + (size_t)m * K + k0 + c * 8);
    }
#pragma unroll
    for (int t = 0; t < BN / 32; t++) {
        int linear = tid + t * 256;
        int m = linear >> 3, c = linear & 7;
        uint32_t sw = (uint32_t)((m * 32 + ((c * 4) ^ ((m & 7) << 2))) * 4);
        CP_ASYNC16(sb + sw, Wb + (size_t)m * K + k0 + c * 8);
    }
}

template <int EPI, int BN, int KB>
__global__ __launch_bounds__(256, 2)
void tc_gemm(const __half* __restrict__ A, const __half* __restrict__ Wt,
             const float* __restrict__ res, void* __restrict__ Cm,
             int M, int N) {
    typedef GemmCfg<BN> CFG;
    const int MT = CFG::MT;
    const int K = KB * 64;
    extern __shared__ __align__(16) char dsm[];
    uint32_t sbase = smem_u32(dsm);

    int tid = threadIdx.x;
    int wid = tid >> 5, lane = tid & 31;
    int warp_m, warp_n;
    if (BN == 128) { warp_m = wid >> 2; warp_n = wid & 3; }
    else           { warp_m = wid >> 1; warp_n = wid & 1; }
    int lr = lane >> 2, lc = lane & 3;

    int swl = (lane & 7) << 2;
    int arow = warp_m * (MT * 16) + (lane & 15);
    uint32_t ahi4 = (uint32_t)((lane >> 4) * 4);
    int brow = warp_n * 32 + ((lane >> 4) << 3) + (lane & 7);
    uint32_t bhi4 = (uint32_t)(((lane >> 3) & 1) * 4);

    const __half* Ab = A + (size_t)blockIdx.y * 128 * K;
    const __half* Wb = Wt + (size_t)blockIdx.x * BN * K;

    float acc[CFG::MT][4][4];
#pragma unroll
    for (int i = 0; i < MT; i++)
#pragma unroll
        for (int j = 0; j < 4; j++)
#pragma unroll
            for (int r = 0; r < 4; r++) acc[i][j][r] = 0.f;

    load_stage<BN, KB>(sbase, sbase + A_STAGE_BYTES, Ab, Wb, 0, tid);
    CP_COMMIT();
    load_stage<BN, KB>(sbase + CFG::STAGE_BYTES, sbase + CFG::STAGE_BYTES + A_STAGE_BYTES,
                       Ab, Wb, 1, tid);
    CP_COMMIT();

#pragma unroll 3
    for (int kb = 0; kb < KB; kb++) {
        int s = kb % 3;
        if (kb + 1 < KB) { CP_WAIT(1); } else { CP_WAIT(0); }
        __syncthreads();
        if (kb + 2 < KB) {
            int sn = (kb + 2) % 3;
            load_stage<BN, KB>(sbase + sn * CFG::STAGE_BYTES,
                               sbase + sn * CFG::STAGE_BYTES + A_STAGE_BYTES,
                               Ab, Wb, kb + 2, tid);
            CP_COMMIT();
        }

        uint32_t as_addr = sbase + s * CFG::STAGE_BYTES;
        uint32_t bs_addr = as_addr + A_STAGE_BYTES;
#pragma unroll
        for (int ks = 0; ks < 4; ks++) {
            uint32_t wa = (uint32_t)(((ks * 8 + ahi4) ^ swl) * 4);
            uint32_t wb = (uint32_t)(((ks * 8 + bhi4) ^ swl) * 4);
            uint32_t afr[CFG::MT][4], bfr[2][4];
#pragma unroll
            for (int mt = 0; mt < MT; mt++)
                ldsm_x4(afr[mt], as_addr + (uint32_t)(arow + mt * 16) * 128 + wa);
#pragma unroll
            for (int ntp = 0; ntp < 2; ntp++)
                ldsm_x4(bfr[ntp], bs_addr + (uint32_t)(brow + ntp * 16) * 128 + wb);
#pragma unroll
            for (int mt = 0; mt < MT; mt++)
#pragma unroll
                for (int nt = 0; nt < 4; nt++)
                    mma_f16(acc[mt][nt], afr[mt], bfr[nt >> 1] + 2 * (nt & 1));
        }
    }

    __syncthreads();
    int gm0 = blockIdx.y * 128 + warp_m * (MT * 16);
    int gn0 = blockIdx.x * BN + warp_n * 32;
#pragma unroll
    for (int mt = 0; mt < MT; mt++) {
#pragma unroll
        for (int nt = 0; nt < 4; nt++) {
            int gm = gm0 + mt * 16 + lr;
            int gn = gn0 + nt * 8 + lc * 2;
#pragma unroll
            for (int half_ = 0; half_ < 2; half_++) {
                int row = gm + half_ * 8;
                size_t off = (size_t)row * N + gn;
                float vx = acc[mt][nt][half_ * 2 + 0];
                float vy = acc[mt][nt][half_ * 2 + 1];
                if (EPI == 1) {
                    float2 rs = *(const float2*)(res + off);
                    float2 v = make_float2(vx + rs.x, vy + rs.y);
                    *(float2*)((float*)Cm + off) = v;
                } else if (EPI == 2) {
                    vx = 0.5f * vx * (1.0f + erff(vx * 0.7071067811865475f));
                    vy = 0.5f * vy * (1.0f + erff(vy * 0.7071067811865475f));
                    *(__half2*)((__half*)Cm + off) = __floats2half2_rn(vx, vy);
                } else {
                    *(__half2*)((__half*)Cm + off) = __floats2half2_rn(vx, vy);
                }
            }
        }
    }
}

// ---------------------------------------------------------------------------
// Tensor-core flash attention (fp16 in / fp32 accum, causal).
// Grid: (T/64, B*H), 128 threads, occupancy 3 (measured sweet spot).
// Softmax in exp2 domain.
// smem halfs: Q [0,4096) | P [4096,8192) | K[2] [8192,16384) | V[2] [16384,24576)
// ---------------------------------------------------------------------------
#define ATTN_SMEM (24576 * 2)   // 48KB

__device__ __forceinline__ void attn_load_kv(uint32_t sb, const __half* __restrict__ kbase,
                                             const __half* __restrict__ vbase,
                                             int j, int s, int tid) {
    uint32_t kdst = sb + (uint32_t)(8192 + s * 4096) * 2;
    uint32_t vdst = sb + (uint32_t)(16384 + s * 4096) * 2;
#pragma unroll
    for (int t = 0; t < 4; t++) {
        int linear = tid + t * 128;
        int r = linear >> 3, c = linear & 7;
        uint32_t sw = (uint32_t)((r * 32 + ((c * 4) ^ ((r & 7) << 2))) * 4);
        size_t go = (size_t)(j * 64 + r) * 3 * C_ + c * 8;
        CP_ASYNC16(kdst + sw, kbase + go);
        CP_ASYNC16(vdst + sw, vbase + go);
    }
}

__global__ __launch_bounds__(128, 3)
void attn_tc(const __half* __restrict__ qkv, __half* __restrict__ y) {
    extern __shared__ __align__(16) char smc[];
    uint32_t sb = smem_u32(smc);

    int qb = gridDim.x - 1 - blockIdx.x;  // longest blocks first
    int bh = blockIdx.y;
    int b = bh / H_, h = bh % H_;
    int tid = threadIdx.x, wid = tid >> 5, lane = tid & 31;
    int lr = lane >> 2, lc = lane & 3;

    const __half* qbase = qkv + (size_t)b * T_ * 3 * C_ + h * HD_;
    const __half* kbase = qbase + C_;
    const __half* vbase = qbase + 2 * C_;

    // load Q tile
#pragma unroll
    for (int t = 0; t < 4; t++) {
        int linear = tid + t * 128;
        int r = linear >> 3, c = linear & 7;
        uint32_t sw = (uint32_t)((r * 32 + ((c * 4) ^ ((r & 7) << 2))) * 4);
        CP_ASYNC16(sb + sw, qbase + (size_t)(qb * 64 + r) * 3 * C_ + c * 8);
    }
    CP_COMMIT();
    attn_load_kv(sb, kbase, vbase, 0, 0, tid);
    CP_COMMIT();

    CP_WAIT(1);
    __syncthreads();

    // ldmatrix constants
    int swl = (lane & 7) << 2;
    int arow = wid * 16 + (lane & 15);
    uint32_t ahi4 = (uint32_t)((lane >> 4) * 4);
    int brow = ((lane >> 4) << 3) + (lane & 7);
    uint32_t bhi4 = (uint32_t)(((lane >> 3) & 1) * 4);
    int vtloc = (((lane >> 3) & 1) << 3) + (lane & 7);
    uint32_t vdc = (uint32_t)(lane >> 4);

    // Q fragments
    uint32_t qfr[4][4];
#pragma unroll
    for (int ks = 0; ks < 4; ks++) {
        uint32_t w = (uint32_t)(((ks * 8 + ahi4) ^ swl) * 4);
        ldsm_x4(qfr[ks], sb + (uint32_t)arow * 128 + w);
    }

    float oacc[8][4];
#pragma unroll
    for (int i = 0; i < 8; i++)
#pragma unroll
        for (int e = 0; e < 4; e++) oacc[i][e] = 0.f;
    float m0 = -1e30f, m1 = -1e30f, l0 = 0.f, l1 = 0.f;

    int r0 = wid * 16 + lr;
    int rg0 = qb * 64 + r0;
    uint32_t psm = sb + 4096 * 2;
    uint32_t* p32 = (uint32_t*)(smc) + 2048;

    // scale folded with log2e: softmax runs in exp2 domain
    const float SC = 0.125f * 1.4426950408889634f;

    for (int j = 0; j <= qb; j++) {
        int s = j & 1;
        if (j < qb) {
            attn_load_kv(sb, kbase, vbase, j + 1, s ^ 1, tid);
            CP_COMMIT();
            CP_WAIT(1);
        } else {
            CP_WAIT(0);
        }
        __syncthreads();

        uint32_t ksm = sb + (uint32_t)(8192 + s * 4096) * 2;
        uint32_t vsm = sb + (uint32_t)(16384 + s * 4096) * 2;

        // S = Q @ K^T
        float sacc[8][4];
#pragma unroll
        for (int nf = 0; nf < 8; nf++)
#pragma unroll
            for (int e = 0; e < 4; e++) sacc[nf][e] = 0.f;
#pragma unroll
        for (int ks = 0; ks < 4; ks++) {
            uint32_t wb = (uint32_t)(((ks * 8 + bhi4) ^ swl) * 4);
#pragma unroll
            for (int ntp = 0; ntp < 4; ntp++) {
                uint32_t kf[4];
                ldsm_x4(kf, ksm + (uint32_t)(brow + ntp * 16) * 128 + wb);
                mma_f16(sacc[2 * ntp],     qfr[ks], kf);
                mma_f16(sacc[2 * ntp + 1], qfr[ks], kf + 2);
            }
        }

        // scale (log2 domain) + causal mask (diagonal tile only)
#pragma unroll
        for (int nf = 0; nf < 8; nf++) {
#pragma unroll
            for (int e = 0; e < 4; e++) {
                float v = sacc[nf][e] * SC;
                if (j == qb) {
                    int col = j * 64 + nf * 8 + 2 * lc + (e & 1);
                    int row = (e < 2) ? rg0 : rg0 + 8;
                    if (col > row) v = -1e30f;
                }
                sacc[nf][e] = v;
            }
        }

        // online softmax (exp2 domain)
        float ml0 = -1e30f, ml1 = -1e30f;
#pragma unroll
        for (int nf = 0; nf < 8; nf++) {
            ml0 = fmaxf(ml0, fmaxf(sacc[nf][0], sacc[nf][1]));
            ml1 = fmaxf(ml1, fmaxf(sacc[nf][2], sacc[nf][3]));
        }
#pragma unroll
        for (int off = 1; off < 4; off <<= 1) {
            ml0 = fmaxf(ml0, __shfl_xor_sync(0xffffffffu, ml0, off));
            ml1 = fmaxf(ml1, __shfl_xor_sync(0xffffffffu, ml1, off));
        }
        float mn0 = fmaxf(m0, ml0), mn1 = fmaxf(m1, ml1);
        float c0 = ex2f(m0 - mn0), c1 = ex2f(m1 - mn1);
        float ls0 = 0.f, ls1 = 0.f;
        int swq = (r0 & 7) << 2;
#pragma unroll
        for (int nf = 0; nf < 8; nf++) {
            float p0 = ex2f(sacc[nf][0] - mn0);
            float p1 = ex2f(sacc[nf][1] - mn0);
            float p2 = ex2f(sacc[nf][2] - mn1);
            float p3 = ex2f(sacc[nf][3] - mn1);
            ls0 += p0 + p1;
            ls1 += p2 + p3;
            int wp = nf * 4 + lc;
            p32[r0 * 32 + (wp ^ swq)]       = h2_as_u32(__floats2half2_rn(p0, p1));
            p32[(r0 + 8) * 32 + (wp ^ swq)] = h2_as_u32(__floats2half2_rn(p2, p3));
        }
#pragma unroll
        for (int off = 1; off < 4; off <<= 1) {
            ls0 += __shfl_xor_sync(0xffffffffu, ls0, off);
            ls1 += __shfl_xor_sync(0xffffffffu, ls1, off);
        }
        l0 = l0 * c0 + ls0;
        l1 = l1 * c1 + ls1;
        m0 = mn0; m1 = mn1;
#pragma unroll
        for (int nf = 0; nf < 8; nf++) {
            oacc[nf][0] *= c0;
            oacc[nf][1] *= c0;
            oacc[nf][2] *= c1;
            oacc[nf][3] *= c1;
        }
        __syncwarp();

        // O += P @ V
#pragma unroll
        for (int ks = 0; ks < 4; ks++) {
            uint32_t pafr[4];
            uint32_t wp = (uint32_t)(((ks * 8 + ahi4) ^ swl) * 4);
            ldsm_x4(pafr, psm + (uint32_t)arow * 128 + wp);
            int trow = ks * 16 + vtloc;
            uint32_t vbaseaddr = vsm + (uint32_t)trow * 128;
            uint32_t vswl = (uint32_t)((trow & 7) << 2);
#pragma unroll
            for (int nfp = 0; nfp < 4; nfp++) {
                uint32_t vf[4];
                uint32_t wv = (uint32_t)((((2 * nfp + vdc) * 4) ^ vswl) * 4);
                ldsm_x4_t(vf, vbaseaddr + wv);
                mma_f16(oacc[2 * nfp],     pafr, vf);
                mma_f16(oacc[2 * nfp + 1], pafr, vf + 2);
            }
        }
        __syncthreads();
    }

    // write y (fp16)
    float inv0 = 1.0f / l0, inv1 = 1.0f / l1;
#pragma unroll
    for (int nf = 0; nf < 8; nf++) {
        int gc = h * HD_ + nf * 8 + 2 * lc;
        size_t o0 = (size_t)(b * T_ + rg0) * C_ + gc;
        size_t o1 = (size_t)(b * T_ + rg0 + 8) * C_ + gc;
        *(__half2*)(y + o0) = __floats2half2_rn(oacc[nf][0] * inv0, oacc[nf][1] * inv0);
        *(__half2*)(y + o1) = __floats2half2_rn(oacc[nf][2] * inv1, oacc[nf][3] * inv1);
    }
}

// ---------------------------------------------------------------------------
// Launch
// ---------------------------------------------------------------------------
extern "C" void kernel_launch(void* const* d_in, const int* in_sizes, int n_in,
                              void* d_out, int out_size) {
    const float* x       = (const float*)d_in[0];
    const float* ln1_g   = (const float*)d_in[1];
    const float* ln1_b   = (const float*)d_in[2];
    const float* W_qkv   = (const float*)d_in[3];
    const float* W_attn  = (const float*)d_in[4];
    const float* ln2_g   = (const float*)d_in[5];
    const float* ln2_b   = (const float*)d_in[6];
    const float* W_fc    = (const float*)d_in[7];
    const float* W_mlp   = (const float*)d_in[8];
    float* out = (float*)d_out;

    __half *ln, *qkv, *yb, *hb, *wq, *wa, *wf, *wm;
    float* x1;
    cudaGetSymbolAddress((void**)&ln, g_ln);
    cudaGetSymbolAddress((void**)&qkv, g_qkv);
    cudaGetSymbolAddress((void**)&yb, g_y);
    cudaGetSymbolAddress((void**)&x1, g_x1);
    cudaGetSymbolAddress((void**)&hb, g_h);
    cudaGetSymbolAddress((void**)&wq, g_wq);
    cudaGetSymbolAddress((void**)&wa, g_wa);
    cudaGetSymbolAddress((void**)&wf, g_wf);
    cudaGetSymbolAddress((void**)&wm, g_wm);

    cudaFuncSetAttribute((tc_gemm<0, 128, 12>), cudaFuncAttributeMaxDynamicSharedMemorySize, GemmCfg<128>::SMEM);
    cudaFuncSetAttribute((tc_gemm<2, 128, 12>), cudaFuncAttributeMaxDynamicSharedMemorySize, GemmCfg<128>::SMEM);
    cudaFuncSetAttribute((tc_gemm<1, 64, 12>),  cudaFuncAttributeMaxDynamicSharedMemorySize, GemmCfg<64>::SMEM);
    cudaFuncSetAttribute((tc_gemm<1, 64, 48>),  cudaFuncAttributeMaxDynamicSharedMemorySize, GemmCfg<64>::SMEM);
    cudaFuncSetAttribute(attn_tc, cudaFuncAttributeMaxDynamicSharedMemorySize, ATTN_SMEM);

    // 0) weights -> fp16 [N,K], single launch
    wconv_all<<<WT_TOT, dim3(32, 8)>>>(W_qkv, W_attn, W_fc, W_mlp, wq, wa, wf, wm);

    // 1) LN1 -> fp16
    ln_kernel<<<BT_ / 8, 256>>>(x, ln1_g, ln1_b, ln);
    // 2) QKV = ln1 @ W_qkv -> fp16
    tc_gemm<0, 128, 12><<<dim3(3 * C_ / 128, BT_ / 128), 256, GemmCfg<128>::SMEM>>>(
        ln, wq, nullptr, qkv, BT_, 3 * C_);
    // 3) causal flash attention (fp16 mma, ldmatrix, exp2 softmax)
    attn_tc<<<dim3(T_ / 64, B_ * H_), 128, ATTN_SMEM>>>(qkv, yb);
    // 4) x1 = x + y @ W_attn_proj (fp32 out), BN=64
    tc_gemm<1, 64, 12><<<dim3(C_ / 64, BT_ / 128), 256, GemmCfg<64>::SMEM>>>(
        yb, wa, x, x1, BT_, C_);
    // 5) LN2 -> fp16
    ln_kernel<<<BT_ / 8, 256>>>(x1, ln2_g, ln2_b, ln);
    // 6) h = gelu(ln2 @ W_fc) -> fp16
    tc_gemm<2, 128, 12><<<dim3(4 * C_ / 128, BT_ / 128), 256, GemmCfg<128>::SMEM>>>(
        ln, wf, nullptr, hb, BT_, 4 * C_);
    // 7) out = x1 + h @ W_mlp_proj (fp32 out), BN=64
    tc_gemm<1, 64, 48><<<dim3(C_ / 64, BT_ / 128), 256, GemmCfg<64>::SMEM>>>(
        hb, wm, x1, out, BT_, C_);
}